// round 15
// baseline (speedup 1.0000x reference)
#include <cuda_runtime.h>
#include <cuda_fp16.h>
#include <math.h>
#include <stdint.h>

#define KK 3
#define NN 16384
#define MM 4096
#define DD 128
#define HH 64

// Scratch (device globals: allocation-free rule)
__device__ __half g_fxh[KK * NN * HH];
__device__ __half g_fzh[KK * MM * HH];
__device__ float g_sn[KK * NN];
__device__ float g_sm[KK * MM];

__device__ __forceinline__ float sp(float v) {
    return fmaxf(v, 0.0f) + log1pf(__expf(-fabsf(v)));
}

// ======================= async / mma helpers (sm_80 PTX only) =======================
__device__ __forceinline__ uint32_t smem_u32_of(const void* p) {
    return (uint32_t)__cvta_generic_to_shared(p);
}
__device__ __forceinline__ void cp16(uint32_t dst, const void* src) {
    asm volatile("cp.async.cg.shared.global [%0], [%1], 16;" :: "r"(dst), "l"(src));
}
__device__ __forceinline__ void cp_commit() {
    asm volatile("cp.async.commit_group;" ::: "memory");
}
template <int N_>
__device__ __forceinline__ void cp_wait() {
    asm volatile("cp.async.wait_group %0;" :: "n"(N_) : "memory");
}
__device__ __forceinline__ void ldsm4(uint32_t* f, uint32_t addr) {
    asm volatile("ldmatrix.sync.aligned.m8n8.x4.shared.b16 {%0,%1,%2,%3}, [%4];"
                 : "=r"(f[0]), "=r"(f[1]), "=r"(f[2]), "=r"(f[3]) : "r"(addr));
}
__device__ __forceinline__ void mma_f16(float* c, const uint32_t* a, uint32_t b0, uint32_t b1) {
    asm volatile(
        "mma.sync.aligned.m16n8k16.row.col.f32.f16.f16.f32 "
        "{%0,%1,%2,%3}, {%4,%5,%6,%7}, {%8,%9}, {%0,%1,%2,%3};"
        : "+f"(c[0]), "+f"(c[1]), "+f"(c[2]), "+f"(c[3])
        : "r"(a[0]), "r"(a[1]), "r"(a[2]), "r"(a[3]), "r"(b0), "r"(b1));
}
__device__ __forceinline__ void mma_f16_zc(float* d, const uint32_t* a, uint32_t b0, uint32_t b1) {
    asm volatile(
        "mma.sync.aligned.m16n8k16.row.col.f32.f16.f16.f32 "
        "{%0,%1,%2,%3}, {%4,%5,%6,%7}, {%8,%9}, {%10,%11,%12,%13};"
        : "=f"(d[0]), "=f"(d[1]), "=f"(d[2]), "=f"(d[3])
        : "r"(a[0]), "r"(a[1]), "r"(a[2]), "r"(a[3]), "r"(b0), "r"(b1),
          "f"(0.0f), "f"(0.0f), "f"(0.0f), "f"(0.0f));
}
__device__ __forceinline__ void st32(uint32_t addr, uint32_t v) {
    asm volatile("st.shared.u32 [%0], %1;" :: "r"(addr), "r"(v) : "memory");
}
__device__ __forceinline__ uint32_t packh2(__half a, __half b) {
    __half2 p = __halves2half2(a, b);
    return *(uint32_t*)&p;
}
__device__ __forceinline__ void stcs2(float* p, float v0, float v1) {
    asm volatile("st.global.cs.v2.f32 [%0], {%1, %2};" :: "l"(p), "f"(v0), "f"(v1) : "memory");
}

// =====================================================================
// Kernel A: phi MLP on tensor cores; W2/W3 prefetched into registers
// during the preceding GEMMs (hides weight LDG latency).
// =====================================================================
#define PRB   384
#define ABUF_OFF 0
#define ABUF_B  (128 * PRB)
#define BBUF_OFF ABUF_B
#define BBUF_B  (64 * PRB)
#define BIAS_OFF (ABUF_B + BBUF_B)
#define SMEM_PHI (BIAS_OFF + 768)

__device__ __forceinline__ void split_st_A(uint32_t base, int row, int c,
                                           float v0, float v1) {
    __half h0 = __float2half(v0), h1 = __float2half(v1);
    __half l0 = __float2half(v0 - __half2float(h0));
    __half l1 = __float2half(v1 - __half2float(h1));
    uint32_t hp = packh2(h0, h1), lp = packh2(l0, l1);
    int r7 = row & 7;
    uint32_t rb = base + (uint32_t)(row * PRB) + (uint32_t)((c & 7) * 2);
    st32(rb + (uint32_t)((((c >> 3)     ) ^ r7) << 4), hp);
    st32(rb + (uint32_t)((((c >> 3) + 8 ) ^ r7) << 4), hp);
    st32(rb + (uint32_t)((((c >> 3) + 16) ^ r7) << 4), lp);
}
__device__ __forceinline__ void split_st_W(uint32_t base, int row, int c,
                                           float v0, float v1) {
    __half h0 = __float2half(v0), h1 = __float2half(v1);
    __half l0 = __float2half(v0 - __half2float(h0));
    __half l1 = __float2half(v1 - __half2float(h1));
    uint32_t hp = packh2(h0, h1), lp = packh2(l0, l1);
    int r7 = row & 7;
    uint32_t rb = base + (uint32_t)(row * PRB) + (uint32_t)((c & 7) * 2);
    st32(rb + (uint32_t)((((c >> 3)     ) ^ r7) << 4), hp);
    st32(rb + (uint32_t)((((c >> 3) + 8 ) ^ r7) << 4), lp);
    st32(rb + (uint32_t)((((c >> 3) + 16) ^ r7) << 4), hp);
}

template <bool INIT>
__device__ __forceinline__ void gemm192(uint32_t a_base, uint32_t b_base,
                                        int lane, float (&acc)[8][4]) {
    const int a_row = lane & 15;
    const int a_cb  = lane >> 4;
    const int b_row = ((lane >> 4) << 3) + (lane & 7);
    const int b_cb  = (lane >> 3) & 1;
    const int a_r7  = a_row & 7;
    #pragma unroll
    for (int ks = 0; ks < 12; ks++) {
        uint32_t af[4];
        ldsm4(af, a_base + (uint32_t)(a_row * PRB)
                  + (uint32_t)((((2 * ks + a_cb) ^ a_r7)) << 4));
        uint32_t bf[4][4];
        #pragma unroll
        for (int nj2 = 0; nj2 < 4; nj2++) {
            int row = nj2 * 16 + b_row;
            ldsm4(bf[nj2], b_base + (uint32_t)(row * PRB)
                      + (uint32_t)((((2 * ks + b_cb) ^ (row & 7))) << 4));
        }
        #pragma unroll
        for (int nj2 = 0; nj2 < 4; nj2++) {
            if (INIT && ks == 0) {
                mma_f16_zc(acc[2 * nj2 + 0], af, bf[nj2][0], bf[nj2][1]);
                mma_f16_zc(acc[2 * nj2 + 1], af, bf[nj2][2], bf[nj2][3]);
            } else {
                mma_f16(acc[2 * nj2 + 0], af, bf[nj2][0], bf[nj2][1]);
                mma_f16(acc[2 * nj2 + 1], af, bf[nj2][2], bf[nj2][3]);
            }
        }
    }
}

__global__ __launch_bounds__(256, 2) void phi_tc(
    const float* __restrict__ x, const float* __restrict__ z,
    const float* __restrict__ W1, const float* __restrict__ b1,
    const float* __restrict__ W2, const float* __restrict__ b2,
    const float* __restrict__ W3, const float* __restrict__ b3) {
    extern __shared__ char sm8[];
    const uint32_t sb = smem_u32_of(sm8);
    const uint32_t aB = sb + ABUF_OFF;
    const uint32_t bB = sb + BBUF_OFF;
    float* biasS = (float*)(sm8 + BIAS_OFF);

    const int t = threadIdx.x;
    const int w = t >> 5, lane = t & 31;
    const int quad = lane >> 2, qid = lane & 3;
    const int k = blockIdx.y;
    const int bx = blockIdx.x;
    const bool isx = (bx < NN / 128);
    const int r0 = (isx ? bx : bx - NN / 128) * 128;
    const float* src = (isx ? x : z) + (size_t)r0 * DD;
    __half* fdst = (isx ? g_fxh + (size_t)k * NN * HH : g_fzh + (size_t)k * MM * HH)
                   + (size_t)r0 * HH;
    float* sdst = (isx ? g_sn + k * NN : g_sm + k * MM) + r0;

    const float* W1k = W1 + k * HH * DD;
    const float* W2k = W2 + k * HH * HH;
    const float* W3k = W3 + k * HH * HH;

    if (t < 64)        biasS[t]       = b1[k * HH + t];
    else if (t < 128)  biasS[t]       = b2[k * HH + (t - 64)];
    else if (t < 192)  biasS[t]       = b3[k * HH + (t - 128)];

    const uint32_t aBw = aB + (uint32_t)(w * 16 * PRB);

    // thread's W-row/col for weight prefetch (16 floats per weight matrix)
    const int wrow = t >> 4, wc = (t & 15) << 2;
    float4 wreg[4];   // prefetch buffer

    float acc[8][4];

    #pragma unroll
    for (int half = 0; half < 2; half++) {
        if (half == 1) __syncthreads();
        #pragma unroll
        for (int i = 0; i < 8; i++) {
            int q = t + i * 256;
            int row = q >> 4, c = (q & 15) << 2;
            float4 v = *(const float4*)(src + (size_t)row * DD + half * 64 + c);
            split_st_A(aB, row, c, v.x, v.y);
            split_st_A(aB, row, c + 2, v.z, v.w);
        }
        #pragma unroll
        for (int i = 0; i < 4; i++) {
            int q = t + i * 256;
            int row = q >> 4, c = (q & 15) << 2;
            float4 v = *(const float4*)(W1k + (size_t)row * DD + half * 64 + c);
            split_st_W(bB, row, c, v.x, v.y);
            split_st_W(bB, row, c + 2, v.z, v.w);
        }
        __syncthreads();
        if (half == 0) {
            gemm192<true>(aBw, bB, lane, acc);
        } else {
            // prefetch W2 rows during GEMM1-part2
            #pragma unroll
            for (int i = 0; i < 4; i++) {
                int q = t + i * 256;
                int row = q >> 4, c = (q & 15) << 2;
                wreg[i] = *(const float4*)(W2k + (size_t)row * HH + c);
            }
            gemm192<false>(aBw, bB, lane, acc);
        }
    }
    __syncthreads();

    #pragma unroll
    for (int nj = 0; nj < 8; nj++) {
        int col = nj * 8 + 2 * qid;
        float v0 = sp(acc[nj][0] + biasS[col]);
        float v1 = sp(acc[nj][1] + biasS[col + 1]);
        float v2 = sp(acc[nj][2] + biasS[col]);
        float v3 = sp(acc[nj][3] + biasS[col + 1]);
        split_st_A(aB, w * 16 + quad, col, v0, v1);
        split_st_A(aB, w * 16 + quad + 8, col, v2, v3);
    }
    #pragma unroll
    for (int i = 0; i < 4; i++) {
        int q = t + i * 256;
        int row = q >> 4, c = (q & 15) << 2;
        split_st_W(bB, row, c, wreg[i].x, wreg[i].y);
        split_st_W(bB, row, c + 2, wreg[i].z, wreg[i].w);
    }
    __syncthreads();

    // prefetch W3 during GEMM2
    #pragma unroll
    for (int i = 0; i < 4; i++) {
        int q = t + i * 256;
        int row = q >> 4, c = (q & 15) << 2;
        wreg[i] = *(const float4*)(W3k + (size_t)row * HH + c);
    }
    gemm192<true>(aBw, bB, lane, acc);
    __syncthreads();

    #pragma unroll
    for (int nj = 0; nj < 8; nj++) {
        int col = nj * 8 + 2 * qid;
        float v0 = sp(acc[nj][0] + biasS[64 + col]);
        float v1 = sp(acc[nj][1] + biasS[64 + col + 1]);
        float v2 = sp(acc[nj][2] + biasS[64 + col]);
        float v3 = sp(acc[nj][3] + biasS[64 + col + 1]);
        split_st_A(aB, w * 16 + quad, col, v0, v1);
        split_st_A(aB, w * 16 + quad + 8, col, v2, v3);
    }
    #pragma unroll
    for (int i = 0; i < 4; i++) {
        int q = t + i * 256;
        int row = q >> 4, c = (q & 15) << 2;
        split_st_W(bB, row, c, wreg[i].x, wreg[i].y);
        split_st_W(bB, row, c + 2, wreg[i].z, wreg[i].w);
    }
    __syncthreads();

    gemm192<true>(aBw, bB, lane, acc);

    float s0 = 0.0f, s1 = 0.0f;
    #pragma unroll
    for (int nj = 0; nj < 8; nj++) {
        int col = nj * 8 + 2 * qid;
        float f0 = acc[nj][0] + biasS[128 + col];
        float f1 = acc[nj][1] + biasS[128 + col + 1];
        float f2 = acc[nj][2] + biasS[128 + col];
        float f3 = acc[nj][3] + biasS[128 + col + 1];
        __half h0 = __float2half(f0), h1 = __float2half(f1);
        __half h2 = __float2half(f2), h3 = __float2half(f3);
        int row0 = w * 16 + quad, row1 = row0 + 8;
        *(uint32_t*)((char*)fdst + ((size_t)row0 * HH + col) * 2) = packh2(h0, h1);
        *(uint32_t*)((char*)fdst + ((size_t)row1 * HH + col) * 2) = packh2(h2, h3);
        float r00 = __half2float(h0), r01 = __half2float(h1);
        float r10 = __half2float(h2), r11 = __half2float(h3);
        s0 += r00 * r00 + r01 * r01;
        s1 += r10 * r10 + r11 * r11;
    }
    s0 += __shfl_xor_sync(0xffffffffu, s0, 1);
    s0 += __shfl_xor_sync(0xffffffffu, s0, 2);
    s1 += __shfl_xor_sync(0xffffffffu, s1, 1);
    s1 += __shfl_xor_sync(0xffffffffu, s1, 2);
    if (qid == 0) {
        sdst[w * 16 + quad] = s0;
        sdst[w * 16 + quad + 8] = s1;
    }
}

// =====================================================================
// Kernel B: r15 = r14 + pre-scaled norms (snS = l*sn, smS = l*sm) and
// the k=2 epilogue fused with the output stores (slice-by-slice).
// =====================================================================
#define NT 128
#define MT 64
#define A_STB (128 * 128)
#define B_STB (64 * 128)
#define STG_B (A_STB + B_STB)
#define OFF_SN2 0
#define OFF_SM2 1536
#define OFF_ST2 2304
#define SMEM_TOT2 (OFF_ST2 + 3 * STG_B)   // 76032

__device__ __forceinline__ void load_chunk(int k, int n0, int m0,
                                           uint32_t stage, int t) {
    const __half* gA = g_fxh + ((size_t)k * NN + n0) * HH;
    const __half* gB = g_fzh + ((size_t)k * MM + m0) * HH;
    #pragma unroll
    for (int i = 0; i < 4; i++) {
        int q = t + i * 256;
        int r = q >> 3, cc = q & 7;
        cp16(stage + r * 128 + (uint32_t)((cc ^ (r & 7)) << 4),
             (const char*)(gA + (size_t)r * HH) + cc * 16);
    }
    #pragma unroll
    for (int i = 0; i < 2; i++) {
        int q = t + i * 256;
        int r = q >> 3, cc = q & 7;
        cp16(stage + A_STB + r * 128 + (uint32_t)((cc ^ (r & 7)) << 4),
             (const char*)(gB + (size_t)r * HH) + cc * 16);
    }
}

// chunk MMA with interleaved epilogue of the previous chunk.
// snS/smS already hold l*sn and l*sm (pre-scaled per kernel k).
template <bool EPI>
__device__ __forceinline__ void chunk_mma_epi(
    uint32_t aB, uint32_t bB,
    float (&acc)[2][4][4], const float (&accP)[2][4][4],
    int kP, const float* snS, const float* smS,
    float l2, float wkk, int nb, int mb, int quad, int qid,
    float (&res)[2][4][4]) {
    float pn00 = 0.f, pn01 = 0.f, pn10 = 0.f, pn11 = 0.f;
    if (EPI) {
        pn00 = snS[kP * 128 + nb + quad];
        pn01 = snS[kP * 128 + nb + quad + 8];
        pn10 = snS[kP * 128 + nb + 16 + quad];
        pn11 = snS[kP * 128 + nb + 16 + quad + 8];
    }
    #pragma unroll
    for (int ks = 0; ks < 4; ks++) {
        const uint32_t kx = (uint32_t)(ks << 5);
        uint32_t af[2][4], bf[2][4];
        ldsm4(af[0], aB ^ kx);
        ldsm4(af[1], (aB + 16 * 128) ^ kx);
        ldsm4(bf[0], bB ^ kx);
        ldsm4(bf[1], (bB + 16 * 128) ^ kx);
        #pragma unroll
        for (int mi = 0; mi < 2; mi++)
            #pragma unroll
            for (int nj2 = 0; nj2 < 2; nj2++) {
                if (ks == 0) {
                    mma_f16_zc(acc[mi][2 * nj2 + 0], af[mi], bf[nj2][0], bf[nj2][1]);
                    mma_f16_zc(acc[mi][2 * nj2 + 1], af[mi], bf[nj2][2], bf[nj2][3]);
                } else {
                    mma_f16(acc[mi][2 * nj2 + 0], af[mi], bf[nj2][0], bf[nj2][1]);
                    mma_f16(acc[mi][2 * nj2 + 1], af[mi], bf[nj2][2], bf[nj2][3]);
                }
            }
        if (EPI) {
            float2 pm2 = *(float2*)&smS[kP * 64 + mb + ks * 8 + 2 * qid];
            float pm0 = pm2.x, pm1 = pm2.y;
            float e0 = exp2f(fmaf(l2, accP[0][ks][0], -(pn00 + pm0)));
            float e1 = exp2f(fmaf(l2, accP[0][ks][1], -(pn00 + pm1)));
            float e2 = exp2f(fmaf(l2, accP[0][ks][2], -(pn01 + pm0)));
            float e3 = exp2f(fmaf(l2, accP[0][ks][3], -(pn01 + pm1)));
            res[0][ks][0] = fmaf(wkk, e0, res[0][ks][0]);
            res[0][ks][1] = fmaf(wkk, e1, res[0][ks][1]);
            res[0][ks][2] = fmaf(wkk, e2, res[0][ks][2]);
            res[0][ks][3] = fmaf(wkk, e3, res[0][ks][3]);
            float f0 = exp2f(fmaf(l2, accP[1][ks][0], -(pn10 + pm0)));
            float f1 = exp2f(fmaf(l2, accP[1][ks][1], -(pn10 + pm1)));
            float f2 = exp2f(fmaf(l2, accP[1][ks][2], -(pn11 + pm0)));
            float f3 = exp2f(fmaf(l2, accP[1][ks][3], -(pn11 + pm1)));
            res[1][ks][0] = fmaf(wkk, f0, res[1][ks][0]);
            res[1][ks][1] = fmaf(wkk, f1, res[1][ks][1]);
            res[1][ks][2] = fmaf(wkk, f2, res[1][ks][2]);
            res[1][ks][3] = fmaf(wkk, f3, res[1][ks][3]);
        }
    }
}

__global__ __launch_bounds__(256, 2) void pair_kernel(
    const float* __restrict__ log_sigma, const float* __restrict__ kw,
    float* __restrict__ out) {
    extern __shared__ char sm8[];
    const uint32_t sb = smem_u32_of(sm8);
    float* snS = (float*)(sm8 + OFF_SN2);
    float* smS = (float*)(sm8 + OFF_SM2);

    const int t = threadIdx.x;
    const int w = t >> 5, lane = t & 31;
    const int quad = lane >> 2, qid = lane & 3;
    const int wn = w & 3, wm = w >> 2;
    const int nb = wn * 32, mb = wm * 32;
    const int m0 = blockIdx.x * MT;
    const int n0 = blockIdx.y * NT;

    load_chunk(0, n0, m0, sb + OFF_ST2 + 0 * STG_B, t);
    load_chunk(1, n0, m0, sb + OFF_ST2 + 1 * STG_B, t);
    load_chunk(2, n0, m0, sb + OFF_ST2 + 2 * STG_B, t);
    cp_commit();

    float w0r = kw[0], w1r = kw[1], w2r = kw[2];
    float wmax = fmaxf(fmaxf(w0r, w1r), w2r);
    float ew0 = __expf(w0r - wmax), ew1 = __expf(w1r - wmax), ew2 = __expf(w2r - wmax);
    float winv = 1.0f / (ew0 + ew1 + ew2);
    float wkv[3] = {ew0 * winv, ew1 * winv, ew2 * winv};
    float lk[3];
    #pragma unroll
    for (int k = 0; k < 3; k++)
        lk[k] = 0.72134752044448170f * exp2f(-log_sigma[k] * 3.3219280948873623f);

    // pre-scaled norms: snS = l*sn, smS = l*sm
    for (int q = t; q < 3 * 128; q += 256) {
        int kq = q >> 7;
        snS[q] = lk[kq] * g_sn[kq * NN + n0 + (q & 127)];
    }
    for (int q = t; q < 3 * 64; q += 256) {
        int kq = q >> 6;
        smS[q] = lk[kq] * g_sm[kq * MM + m0 + (q & 63)];
    }

    float res[2][4][4];
    #pragma unroll
    for (int mi = 0; mi < 2; mi++)
        #pragma unroll
        for (int nj = 0; nj < 4; nj++)
            #pragma unroll
            for (int r = 0; r < 4; r++) res[mi][nj][r] = 0.0f;

    // XOR-identity ldsm base addresses: addr(ks) = base0 ^ (ks << 5)
    const int a_row = nb + (lane & 15);
    const int b_row = mb + ((lane >> 4) << 3) + (lane & 7);
    const uint32_t a0 = sb + OFF_ST2 + (uint32_t)(a_row * 128)
                        + (uint32_t)((((lane >> 4) ^ (a_row & 7))) << 4);
    const uint32_t b0 = sb + OFF_ST2 + A_STB + (uint32_t)(b_row * 128)
                        + (uint32_t)(((((lane >> 3) & 1) ^ (b_row & 7))) << 4);

    cp_wait<0>();
    __syncthreads();

    float accA[2][4][4], accB[2][4][4];

    // k=0: MMA only
    chunk_mma_epi<false>(a0, b0, accA, accB, 0, snS, smS,
                         0.f, 0.f, nb, mb, quad, qid, res);
    // k=1: MMA + epilogue of k=0
    chunk_mma_epi<true>(a0 + STG_B, b0 + STG_B, accB, accA, 0, snS, smS,
                        2.0f * lk[0], wkv[0], nb, mb, quad, qid, res);
    // k=2: MMA + epilogue of k=1
    chunk_mma_epi<true>(a0 + 2 * STG_B, b0 + 2 * STG_B, accA, accB, 1, snS, smS,
                        2.0f * lk[1], wkv[1], nb, mb, quad, qid, res);

    // epilogue of k=2 fused with stores (slice by slice; EX2 overlaps STG)
    {
        float l2 = 2.0f * lk[2], wkk = wkv[2];
        float pn00 = snS[2 * 128 + nb + quad];
        float pn01 = snS[2 * 128 + nb + quad + 8];
        float pn10 = snS[2 * 128 + nb + 16 + quad];
        float pn11 = snS[2 * 128 + nb + 16 + quad + 8];
        float* ob = out + (size_t)(n0 + nb + quad) * MM + m0 + mb + 2 * qid;
        #pragma unroll
        for (int nj = 0; nj < 4; nj++) {
            float2 pm2 = *(float2*)&smS[2 * 64 + mb + nj * 8 + 2 * qid];
            float pm0 = pm2.x, pm1 = pm2.y;
            float r00 = fmaf(wkk, exp2f(fmaf(l2, accA[0][nj][0], -(pn00 + pm0))), res[0][nj][0]);
            float r01 = fmaf(wkk, exp2f(fmaf(l2, accA[0][nj][1], -(pn00 + pm1))), res[0][nj][1]);
            float r02 = fmaf(wkk, exp2f(fmaf(l2, accA[0][nj][2], -(pn01 + pm0))), res[0][nj][2]);
            float r03 = fmaf(wkk, exp2f(fmaf(l2, accA[0][nj][3], -(pn01 + pm1))), res[0][nj][3]);
            stcs2(ob + nj * 8, r00, r01);
            stcs2(ob + nj * 8 + (size_t)8 * MM, r02, r03);
            float r10 = fmaf(wkk, exp2f(fmaf(l2, accA[1][nj][0], -(pn10 + pm0))), res[1][nj][0]);
            float r11 = fmaf(wkk, exp2f(fmaf(l2, accA[1][nj][1], -(pn10 + pm1))), res[1][nj][1]);
            float r12 = fmaf(wkk, exp2f(fmaf(l2, accA[1][nj][2], -(pn11 + pm0))), res[1][nj][2]);
            float r13 = fmaf(wkk, exp2f(fmaf(l2, accA[1][nj][3], -(pn11 + pm1))), res[1][nj][3]);
            stcs2(ob + nj * 8 + (size_t)16 * MM, r10, r11);
            stcs2(ob + nj * 8 + (size_t)24 * MM, r12, r13);
        }
    }
}

extern "C" void kernel_launch(void* const* d_in, const int* in_sizes, int n_in,
                              void* d_out, int out_size) {
    const float* x  = (const float*)d_in[0];
    const float* z  = (const float*)d_in[1];
    const float* W1 = (const float*)d_in[2];
    const float* b1 = (const float*)d_in[3];
    const float* W2 = (const float*)d_in[4];
    const float* b2 = (const float*)d_in[5];
    const float* W3 = (const float*)d_in[6];
    const float* b3 = (const float*)d_in[7];
    const float* ls = (const float*)d_in[8];
    const float* kwp = (const float*)d_in[9];
    float* out = (float*)d_out;

    cudaFuncSetAttribute(phi_tc, cudaFuncAttributeMaxDynamicSharedMemorySize, SMEM_PHI);
    cudaFuncSetAttribute(pair_kernel, cudaFuncAttributeMaxDynamicSharedMemorySize, SMEM_TOT2);

    phi_tc<<<dim3((NN + MM) / 128, 3), 256, SMEM_PHI>>>(x, z, W1, b1, W2, b2, W3, b3);
    pair_kernel<<<dim3(MM / MT, NN / NT), 256, SMEM_TOT2>>>(ls, kwp, out);
}

// round 16
// speedup vs baseline: 1.0319x; 1.0319x over previous
#include <cuda_runtime.h>
#include <cuda_fp16.h>
#include <math.h>
#include <stdint.h>

#define KK 3
#define NN 16384
#define MM 4096
#define DD 128
#define HH 64

// Scratch (device globals: allocation-free rule)
// Features fp16; norms in fp32 from the fp16-ROUNDED values (consistency:
// sq = sn + sm - 2*dot == |x_hat - z_hat|^2, error decays with exp).
__device__ __half g_fxh[KK * NN * HH];
__device__ __half g_fzh[KK * MM * HH];
__device__ float g_sn[KK * NN];
__device__ float g_sm[KK * MM];

__device__ __forceinline__ float sp(float v) {
    return fmaxf(v, 0.0f) + log1pf(__expf(-fabsf(v)));
}

// ======================= async / mma helpers (sm_80 PTX only) =======================
__device__ __forceinline__ uint32_t smem_u32_of(const void* p) {
    return (uint32_t)__cvta_generic_to_shared(p);
}
__device__ __forceinline__ void cp16(uint32_t dst, const void* src) {
    asm volatile("cp.async.cg.shared.global [%0], [%1], 16;" :: "r"(dst), "l"(src));
}
__device__ __forceinline__ void cp_commit() {
    asm volatile("cp.async.commit_group;" ::: "memory");
}
template <int N_>
__device__ __forceinline__ void cp_wait() {
    asm volatile("cp.async.wait_group %0;" :: "n"(N_) : "memory");
}
__device__ __forceinline__ void ldsm4(uint32_t* f, uint32_t addr) {
    asm volatile("ldmatrix.sync.aligned.m8n8.x4.shared.b16 {%0,%1,%2,%3}, [%4];"
                 : "=r"(f[0]), "=r"(f[1]), "=r"(f[2]), "=r"(f[3]) : "r"(addr));
}
__device__ __forceinline__ void mma_f16(float* c, const uint32_t* a, uint32_t b0, uint32_t b1) {
    asm volatile(
        "mma.sync.aligned.m16n8k16.row.col.f32.f16.f16.f32 "
        "{%0,%1,%2,%3}, {%4,%5,%6,%7}, {%8,%9}, {%0,%1,%2,%3};"
        : "+f"(c[0]), "+f"(c[1]), "+f"(c[2]), "+f"(c[3])
        : "r"(a[0]), "r"(a[1]), "r"(a[2]), "r"(a[3]), "r"(b0), "r"(b1));
}
// d = a*b + 0 (RZ accumulator: no init MOVs)
__device__ __forceinline__ void mma_f16_zc(float* d, const uint32_t* a, uint32_t b0, uint32_t b1) {
    asm volatile(
        "mma.sync.aligned.m16n8k16.row.col.f32.f16.f16.f32 "
        "{%0,%1,%2,%3}, {%4,%5,%6,%7}, {%8,%9}, {%10,%11,%12,%13};"
        : "=f"(d[0]), "=f"(d[1]), "=f"(d[2]), "=f"(d[3])
        : "r"(a[0]), "r"(a[1]), "r"(a[2]), "r"(a[3]), "r"(b0), "r"(b1),
          "f"(0.0f), "f"(0.0f), "f"(0.0f), "f"(0.0f));
}
__device__ __forceinline__ void st32(uint32_t addr, uint32_t v) {
    asm volatile("st.shared.u32 [%0], %1;" :: "r"(addr), "r"(v) : "memory");
}
__device__ __forceinline__ uint32_t packh2(__half a, __half b) {
    __half2 p = __halves2half2(a, b);
    return *(uint32_t*)&p;
}
__device__ __forceinline__ void stcs2(float* p, float v0, float v1) {
    asm volatile("st.global.cs.v2.f32 [%0], {%1, %2};" :: "l"(p), "f"(v0), "f"(v1) : "memory");
}

// =====================================================================
// Kernel A: phi MLP on tensor cores; W2/W3 prefetched into registers
// during the preceding GEMMs (r15, kept — measured 39us).
// =====================================================================
#define PRB   384
#define ABUF_OFF 0
#define ABUF_B  (128 * PRB)
#define BBUF_OFF ABUF_B
#define BBUF_B  (64 * PRB)
#define BIAS_OFF (ABUF_B + BBUF_B)
#define SMEM_PHI (BIAS_OFF + 768)

__device__ __forceinline__ void split_st_A(uint32_t base, int row, int c,
                                           float v0, float v1) {
    __half h0 = __float2half(v0), h1 = __float2half(v1);
    __half l0 = __float2half(v0 - __half2float(h0));
    __half l1 = __float2half(v1 - __half2float(h1));
    uint32_t hp = packh2(h0, h1), lp = packh2(l0, l1);
    int r7 = row & 7;
    uint32_t rb = base + (uint32_t)(row * PRB) + (uint32_t)((c & 7) * 2);
    st32(rb + (uint32_t)((((c >> 3)     ) ^ r7) << 4), hp);
    st32(rb + (uint32_t)((((c >> 3) + 8 ) ^ r7) << 4), hp);
    st32(rb + (uint32_t)((((c >> 3) + 16) ^ r7) << 4), lp);
}
__device__ __forceinline__ void split_st_W(uint32_t base, int row, int c,
                                           float v0, float v1) {
    __half h0 = __float2half(v0), h1 = __float2half(v1);
    __half l0 = __float2half(v0 - __half2float(h0));
    __half l1 = __float2half(v1 - __half2float(h1));
    uint32_t hp = packh2(h0, h1), lp = packh2(l0, l1);
    int r7 = row & 7;
    uint32_t rb = base + (uint32_t)(row * PRB) + (uint32_t)((c & 7) * 2);
    st32(rb + (uint32_t)((((c >> 3)     ) ^ r7) << 4), hp);
    st32(rb + (uint32_t)((((c >> 3) + 8 ) ^ r7) << 4), lp);
    st32(rb + (uint32_t)((((c >> 3) + 16) ^ r7) << 4), hp);
}

template <bool INIT>
__device__ __forceinline__ void gemm192(uint32_t a_base, uint32_t b_base,
                                        int lane, float (&acc)[8][4]) {
    const int a_row = lane & 15;
    const int a_cb  = lane >> 4;
    const int b_row = ((lane >> 4) << 3) + (lane & 7);
    const int b_cb  = (lane >> 3) & 1;
    const int a_r7  = a_row & 7;
    #pragma unroll
    for (int ks = 0; ks < 12; ks++) {
        uint32_t af[4];
        ldsm4(af, a_base + (uint32_t)(a_row * PRB)
                  + (uint32_t)((((2 * ks + a_cb) ^ a_r7)) << 4));
        uint32_t bf[4][4];
        #pragma unroll
        for (int nj2 = 0; nj2 < 4; nj2++) {
            int row = nj2 * 16 + b_row;
            ldsm4(bf[nj2], b_base + (uint32_t)(row * PRB)
                      + (uint32_t)((((2 * ks + b_cb) ^ (row & 7))) << 4));
        }
        #pragma unroll
        for (int nj2 = 0; nj2 < 4; nj2++) {
            if (INIT && ks == 0) {
                mma_f16_zc(acc[2 * nj2 + 0], af, bf[nj2][0], bf[nj2][1]);
                mma_f16_zc(acc[2 * nj2 + 1], af, bf[nj2][2], bf[nj2][3]);
            } else {
                mma_f16(acc[2 * nj2 + 0], af, bf[nj2][0], bf[nj2][1]);
                mma_f16(acc[2 * nj2 + 1], af, bf[nj2][2], bf[nj2][3]);
            }
        }
    }
}

__global__ __launch_bounds__(256, 2) void phi_tc(
    const float* __restrict__ x, const float* __restrict__ z,
    const float* __restrict__ W1, const float* __restrict__ b1,
    const float* __restrict__ W2, const float* __restrict__ b2,
    const float* __restrict__ W3, const float* __restrict__ b3) {
    extern __shared__ char sm8[];
    const uint32_t sb = smem_u32_of(sm8);
    const uint32_t aB = sb + ABUF_OFF;
    const uint32_t bB = sb + BBUF_OFF;
    float* biasS = (float*)(sm8 + BIAS_OFF);

    const int t = threadIdx.x;
    const int w = t >> 5, lane = t & 31;
    const int quad = lane >> 2, qid = lane & 3;
    const int k = blockIdx.y;
    const int bx = blockIdx.x;
    const bool isx = (bx < NN / 128);
    const int r0 = (isx ? bx : bx - NN / 128) * 128;
    const float* src = (isx ? x : z) + (size_t)r0 * DD;
    __half* fdst = (isx ? g_fxh + (size_t)k * NN * HH : g_fzh + (size_t)k * MM * HH)
                   + (size_t)r0 * HH;
    float* sdst = (isx ? g_sn + k * NN : g_sm + k * MM) + r0;

    const float* W1k = W1 + k * HH * DD;
    const float* W2k = W2 + k * HH * HH;
    const float* W3k = W3 + k * HH * HH;

    if (t < 64)        biasS[t]       = b1[k * HH + t];
    else if (t < 128)  biasS[t]       = b2[k * HH + (t - 64)];
    else if (t < 192)  biasS[t]       = b3[k * HH + (t - 128)];

    const uint32_t aBw = aB + (uint32_t)(w * 16 * PRB);

    float4 wreg[4];
    float acc[8][4];

    #pragma unroll
    for (int half = 0; half < 2; half++) {
        if (half == 1) __syncthreads();
        #pragma unroll
        for (int i = 0; i < 8; i++) {
            int q = t + i * 256;
            int row = q >> 4, c = (q & 15) << 2;
            float4 v = *(const float4*)(src + (size_t)row * DD + half * 64 + c);
            split_st_A(aB, row, c, v.x, v.y);
            split_st_A(aB, row, c + 2, v.z, v.w);
        }
        #pragma unroll
        for (int i = 0; i < 4; i++) {
            int q = t + i * 256;
            int row = q >> 4, c = (q & 15) << 2;
            float4 v = *(const float4*)(W1k + (size_t)row * DD + half * 64 + c);
            split_st_W(bB, row, c, v.x, v.y);
            split_st_W(bB, row, c + 2, v.z, v.w);
        }
        __syncthreads();
        if (half == 0) {
            gemm192<true>(aBw, bB, lane, acc);
        } else {
            #pragma unroll
            for (int i = 0; i < 4; i++) {
                int q = t + i * 256;
                int row = q >> 4, c = (q & 15) << 2;
                wreg[i] = *(const float4*)(W2k + (size_t)row * HH + c);
            }
            gemm192<false>(aBw, bB, lane, acc);
        }
    }
    __syncthreads();

    #pragma unroll
    for (int nj = 0; nj < 8; nj++) {
        int col = nj * 8 + 2 * qid;
        float v0 = sp(acc[nj][0] + biasS[col]);
        float v1 = sp(acc[nj][1] + biasS[col + 1]);
        float v2 = sp(acc[nj][2] + biasS[col]);
        float v3 = sp(acc[nj][3] + biasS[col + 1]);
        split_st_A(aB, w * 16 + quad, col, v0, v1);
        split_st_A(aB, w * 16 + quad + 8, col, v2, v3);
    }
    #pragma unroll
    for (int i = 0; i < 4; i++) {
        int q = t + i * 256;
        int row = q >> 4, c = (q & 15) << 2;
        split_st_W(bB, row, c, wreg[i].x, wreg[i].y);
        split_st_W(bB, row, c + 2, wreg[i].z, wreg[i].w);
    }
    __syncthreads();

    #pragma unroll
    for (int i = 0; i < 4; i++) {
        int q = t + i * 256;
        int row = q >> 4, c = (q & 15) << 2;
        wreg[i] = *(const float4*)(W3k + (size_t)row * HH + c);
    }
    gemm192<true>(aBw, bB, lane, acc);
    __syncthreads();

    #pragma unroll
    for (int nj = 0; nj < 8; nj++) {
        int col = nj * 8 + 2 * qid;
        float v0 = sp(acc[nj][0] + biasS[64 + col]);
        float v1 = sp(acc[nj][1] + biasS[64 + col + 1]);
        float v2 = sp(acc[nj][2] + biasS[64 + col]);
        float v3 = sp(acc[nj][3] + biasS[64 + col + 1]);
        split_st_A(aB, w * 16 + quad, col, v0, v1);
        split_st_A(aB, w * 16 + quad + 8, col, v2, v3);
    }
    #pragma unroll
    for (int i = 0; i < 4; i++) {
        int q = t + i * 256;
        int row = q >> 4, c = (q & 15) << 2;
        split_st_W(bB, row, c, wreg[i].x, wreg[i].y);
        split_st_W(bB, row, c + 2, wreg[i].z, wreg[i].w);
    }
    __syncthreads();

    gemm192<true>(aBw, bB, lane, acc);

    float s0 = 0.0f, s1 = 0.0f;
    #pragma unroll
    for (int nj = 0; nj < 8; nj++) {
        int col = nj * 8 + 2 * qid;
        float f0 = acc[nj][0] + biasS[128 + col];
        float f1 = acc[nj][1] + biasS[128 + col + 1];
        float f2 = acc[nj][2] + biasS[128 + col];
        float f3 = acc[nj][3] + biasS[128 + col + 1];
        __half h0 = __float2half(f0), h1 = __float2half(f1);
        __half h2 = __float2half(f2), h3 = __float2half(f3);
        int row0 = w * 16 + quad, row1 = row0 + 8;
        *(uint32_t*)((char*)fdst + ((size_t)row0 * HH + col) * 2) = packh2(h0, h1);
        *(uint32_t*)((char*)fdst + ((size_t)row1 * HH + col) * 2) = packh2(h2, h3);
        float r00 = __half2float(h0), r01 = __half2float(h1);
        float r10 = __half2float(h2), r11 = __half2float(h3);
        s0 += r00 * r00 + r01 * r01;
        s1 += r10 * r10 + r11 * r11;
    }
    s0 += __shfl_xor_sync(0xffffffffu, s0, 1);
    s0 += __shfl_xor_sync(0xffffffffu, s0, 2);
    s1 += __shfl_xor_sync(0xffffffffu, s1, 1);
    s1 += __shfl_xor_sync(0xffffffffu, s1, 2);
    if (qid == 0) {
        sdst[w * 16 + quad] = s0;
        sdst[w * 16 + quad + 8] = s1;
    }
}

// =====================================================================
// Kernel B: exact r14 structure (best measured: 134.2us) + FIRST-write
// res assignment in the k=1 epilogue (kills the 32-MOV res init).
// =====================================================================
#define NT 128
#define MT 64
#define A_STB (128 * 128)
#define B_STB (64 * 128)
#define STG_B (A_STB + B_STB)
#define OFF_SN2 0
#define OFF_SM2 1536
#define OFF_ST2 2304
#define SMEM_TOT2 (OFF_ST2 + 3 * STG_B)   // 76032

__device__ __forceinline__ void load_chunk(int k, int n0, int m0,
                                           uint32_t stage, int t) {
    const __half* gA = g_fxh + ((size_t)k * NN + n0) * HH;
    const __half* gB = g_fzh + ((size_t)k * MM + m0) * HH;
    #pragma unroll
    for (int i = 0; i < 4; i++) {
        int q = t + i * 256;
        int r = q >> 3, cc = q & 7;
        cp16(stage + r * 128 + (uint32_t)((cc ^ (r & 7)) << 4),
             (const char*)(gA + (size_t)r * HH) + cc * 16);
    }
    #pragma unroll
    for (int i = 0; i < 2; i++) {
        int q = t + i * 256;
        int r = q >> 3, cc = q & 7;
        cp16(stage + A_STB + r * 128 + (uint32_t)((cc ^ (r & 7)) << 4),
             (const char*)(gB + (size_t)r * HH) + cc * 16);
    }
}

// chunk MMA; optionally interleaves the epilogue of the PREVIOUS chunk,
// one nj slice per ks step. FIRST: res is assigned (first write).
template <bool EPI, bool FIRST>
__device__ __forceinline__ void chunk_mma_epi(
    uint32_t aB, uint32_t bB,
    float (&acc)[2][4][4], const float (&accP)[2][4][4],
    int kP, const float* snS, const float* smS,
    float l, float wkk, int nb, int mb, int quad, int qid,
    float (&res)[2][4][4]) {
    float l2 = 2.0f * l;
    float pn00 = 0.f, pn01 = 0.f, pn10 = 0.f, pn11 = 0.f;
    if (EPI) {
        pn00 = l * snS[kP * 128 + nb + quad];
        pn01 = l * snS[kP * 128 + nb + quad + 8];
        pn10 = l * snS[kP * 128 + nb + 16 + quad];
        pn11 = l * snS[kP * 128 + nb + 16 + quad + 8];
    }
    #pragma unroll
    for (int ks = 0; ks < 4; ks++) {
        const uint32_t kx = (uint32_t)(ks << 5);
        uint32_t af[2][4], bf[2][4];
        ldsm4(af[0], aB ^ kx);
        ldsm4(af[1], (aB + 16 * 128) ^ kx);
        ldsm4(bf[0], bB ^ kx);
        ldsm4(bf[1], (bB + 16 * 128) ^ kx);
        #pragma unroll
        for (int mi = 0; mi < 2; mi++)
            #pragma unroll
            for (int nj2 = 0; nj2 < 2; nj2++) {
                if (ks == 0) {
                    mma_f16_zc(acc[mi][2 * nj2 + 0], af[mi], bf[nj2][0], bf[nj2][1]);
                    mma_f16_zc(acc[mi][2 * nj2 + 1], af[mi], bf[nj2][2], bf[nj2][3]);
                } else {
                    mma_f16(acc[mi][2 * nj2 + 0], af[mi], bf[nj2][0], bf[nj2][1]);
                    mma_f16(acc[mi][2 * nj2 + 1], af[mi], bf[nj2][2], bf[nj2][3]);
                }
            }
        if (EPI) {
            float2 pm2 = *(float2*)&smS[kP * 64 + mb + ks * 8 + 2 * qid];
            float pm0 = l * pm2.x, pm1 = l * pm2.y;
            float e0 = exp2f(fmaf(l2, accP[0][ks][0], -(pn00 + pm0)));
            float e1 = exp2f(fmaf(l2, accP[0][ks][1], -(pn00 + pm1)));
            float e2 = exp2f(fmaf(l2, accP[0][ks][2], -(pn01 + pm0)));
            float e3 = exp2f(fmaf(l2, accP[0][ks][3], -(pn01 + pm1)));
            float f0 = exp2f(fmaf(l2, accP[1][ks][0], -(pn10 + pm0)));
            float f1 = exp2f(fmaf(l2, accP[1][ks][1], -(pn10 + pm1)));
            float f2 = exp2f(fmaf(l2, accP[1][ks][2], -(pn11 + pm0)));
            float f3 = exp2f(fmaf(l2, accP[1][ks][3], -(pn11 + pm1)));
            if (FIRST) {
                res[0][ks][0] = wkk * e0; res[0][ks][1] = wkk * e1;
                res[0][ks][2] = wkk * e2; res[0][ks][3] = wkk * e3;
                res[1][ks][0] = wkk * f0; res[1][ks][1] = wkk * f1;
                res[1][ks][2] = wkk * f2; res[1][ks][3] = wkk * f3;
            } else {
                res[0][ks][0] = fmaf(wkk, e0, res[0][ks][0]);
                res[0][ks][1] = fmaf(wkk, e1, res[0][ks][1]);
                res[0][ks][2] = fmaf(wkk, e2, res[0][ks][2]);
                res[0][ks][3] = fmaf(wkk, e3, res[0][ks][3]);
                res[1][ks][0] = fmaf(wkk, f0, res[1][ks][0]);
                res[1][ks][1] = fmaf(wkk, f1, res[1][ks][1]);
                res[1][ks][2] = fmaf(wkk, f2, res[1][ks][2]);
                res[1][ks][3] = fmaf(wkk, f3, res[1][ks][3]);
            }
        }
    }
}

// standalone epilogue (for the last chunk)
__device__ __forceinline__ void epi_full(
    const float (&accP)[2][4][4], int kP, const float* snS, const float* smS,
    float l, float wkk, int nb, int mb, int quad, int qid,
    float (&res)[2][4][4]) {
    float l2 = 2.0f * l;
    float pn[2][2];
    pn[0][0] = l * snS[kP * 128 + nb + quad];
    pn[0][1] = l * snS[kP * 128 + nb + quad + 8];
    pn[1][0] = l * snS[kP * 128 + nb + 16 + quad];
    pn[1][1] = l * snS[kP * 128 + nb + 16 + quad + 8];
    #pragma unroll
    for (int nj = 0; nj < 4; nj++) {
        float2 pm2 = *(float2*)&smS[kP * 64 + mb + nj * 8 + 2 * qid];
        float pm0 = l * pm2.x, pm1 = l * pm2.y;
        #pragma unroll
        for (int mi = 0; mi < 2; mi++) {
            float e0 = exp2f(fmaf(l2, accP[mi][nj][0], -(pn[mi][0] + pm0)));
            float e1 = exp2f(fmaf(l2, accP[mi][nj][1], -(pn[mi][0] + pm1)));
            float e2 = exp2f(fmaf(l2, accP[mi][nj][2], -(pn[mi][1] + pm0)));
            float e3 = exp2f(fmaf(l2, accP[mi][nj][3], -(pn[mi][1] + pm1)));
            res[mi][nj][0] = fmaf(wkk, e0, res[mi][nj][0]);
            res[mi][nj][1] = fmaf(wkk, e1, res[mi][nj][1]);
            res[mi][nj][2] = fmaf(wkk, e2, res[mi][nj][2]);
            res[mi][nj][3] = fmaf(wkk, e3, res[mi][nj][3]);
        }
    }
}

__global__ __launch_bounds__(256, 2) void pair_kernel(
    const float* __restrict__ log_sigma, const float* __restrict__ kw,
    float* __restrict__ out) {
    extern __shared__ char sm8[];
    const uint32_t sb = smem_u32_of(sm8);
    float* snS = (float*)(sm8 + OFF_SN2);
    float* smS = (float*)(sm8 + OFF_SM2);

    const int t = threadIdx.x;
    const int w = t >> 5, lane = t & 31;
    const int quad = lane >> 2, qid = lane & 3;
    const int wn = w & 3, wm = w >> 2;
    const int nb = wn * 32, mb = wm * 32;
    const int m0 = blockIdx.x * MT;
    const int n0 = blockIdx.y * NT;

    load_chunk(0, n0, m0, sb + OFF_ST2 + 0 * STG_B, t);
    load_chunk(1, n0, m0, sb + OFF_ST2 + 1 * STG_B, t);
    load_chunk(2, n0, m0, sb + OFF_ST2 + 2 * STG_B, t);
    cp_commit();

    for (int q = t; q < 3 * 128; q += 256)
        snS[q] = g_sn[(q >> 7) * NN + n0 + (q & 127)];
    for (int q = t; q < 3 * 64; q += 256)
        smS[q] = g_sm[(q >> 6) * MM + m0 + (q & 63)];

    float w0r = kw[0], w1r = kw[1], w2r = kw[2];
    float wmax = fmaxf(fmaxf(w0r, w1r), w2r);
    float ew0 = __expf(w0r - wmax), ew1 = __expf(w1r - wmax), ew2 = __expf(w2r - wmax);
    float winv = 1.0f / (ew0 + ew1 + ew2);
    float wkv[3] = {ew0 * winv, ew1 * winv, ew2 * winv};
    float lk[3];
    #pragma unroll
    for (int k = 0; k < 3; k++)
        lk[k] = 0.72134752044448170f * exp2f(-log_sigma[k] * 3.3219280948873623f);

    // XOR-identity ldsm base addresses: addr(ks) = base0 ^ (ks << 5)
    const int a_row = nb + (lane & 15);
    const int b_row = mb + ((lane >> 4) << 3) + (lane & 7);
    const uint32_t a0 = sb + OFF_ST2 + (uint32_t)(a_row * 128)
                        + (uint32_t)((((lane >> 4) ^ (a_row & 7))) << 4);
    const uint32_t b0 = sb + OFF_ST2 + A_STB + (uint32_t)(b_row * 128)
                        + (uint32_t)(((((lane >> 3) & 1) ^ (b_row & 7))) << 4);

    cp_wait<0>();
    __syncthreads();

    float res[2][4][4];
    float accA[2][4][4], accB[2][4][4];

    // k=0: MMA only
    chunk_mma_epi<false, false>(a0, b0, accA, accB, 0, snS, smS,
                                0.f, 0.f, nb, mb, quad, qid, res);
    // k=1: MMA + epilogue of k=0 (FIRST write of res)
    chunk_mma_epi<true, true>(a0 + STG_B, b0 + STG_B, accB, accA, 0, snS, smS,
                              lk[0], wkv[0], nb, mb, quad, qid, res);
    // k=2: MMA + epilogue of k=1
    chunk_mma_epi<true, false>(a0 + 2 * STG_B, b0 + 2 * STG_B, accA, accB, 1, snS, smS,
                               lk[1], wkv[1], nb, mb, quad, qid, res);
    // epilogue of k=2
    epi_full(accA, 2, snS, smS, lk[2], wkv[2], nb, mb, quad, qid, res);

    // store: rows = n, cols = m; streaming (evict-first)
    #pragma unroll
    for (int mi = 0; mi < 2; mi++) {
        int nrow = n0 + nb + mi * 16 + quad;
        #pragma unroll
        for (int nj = 0; nj < 4; nj++) {
            float* p0 = out + (size_t)nrow * MM + m0 + mb + nj * 8 + 2 * qid;
            stcs2(p0, res[mi][nj][0], res[mi][nj][1]);
            stcs2(p0 + (size_t)8 * MM, res[mi][nj][2], res[mi][nj][3]);
        }
    }
}

extern "C" void kernel_launch(void* const* d_in, const int* in_sizes, int n_in,
                              void* d_out, int out_size) {
    const float* x  = (const float*)d_in[0];
    const float* z  = (const float*)d_in[1];
    const float* W1 = (const float*)d_in[2];
    const float* b1 = (const float*)d_in[3];
    const float* W2 = (const float*)d_in[4];
    const float* b2 = (const float*)d_in[5];
    const float* W3 = (const float*)d_in[6];
    const float* b3 = (const float*)d_in[7];
    const float* ls = (const float*)d_in[8];
    const float* kwp = (const float*)d_in[9];
    float* out = (float*)d_out;

    cudaFuncSetAttribute(phi_tc, cudaFuncAttributeMaxDynamicSharedMemorySize, SMEM_PHI);
    cudaFuncSetAttribute(pair_kernel, cudaFuncAttributeMaxDynamicSharedMemorySize, SMEM_TOT2);

    phi_tc<<<dim3((NN + MM) / 128, 3), 256, SMEM_PHI>>>(x, z, W1, b1, W2, b2, W3, b3);
    pair_kernel<<<dim3(MM / MT, NN / NT), 256, SMEM_TOT2>>>(ls, kwp, out);
}